// round 16
// baseline (speedup 1.0000x reference)
#include <cuda_runtime.h>
#include <cstdint>

// ---------------------------------------------------------------------------
// MPEdgeNodeBlock — TF32 mma.sync, K-chunked double-buffered layers.
// R15: big (NOUT=192) layers use 128-row tiles with 512 threads (16 warps,
// 1 CTA/SM — same warp count as R14's 2x256, but B staged once per 128 rows:
// -37% LDGSTS issue, -50% B L2 traffic).  Out layers & proj keep R14 shape.
// ---------------------------------------------------------------------------
#define N_NODES  25000
#define NODE_PAD 25088            // 196 * 128
#define N_EDGES  200000
#define EDGE_PAD 200064           // 1563 * 128
#define IN_F     64
#define OUT_F    64
#define HDIM     192

// -------------------- scratch (device globals; no runtime alloc) ------------
__device__ __align__(16) float g_Xr[NODE_PAD * HDIM];
__device__ __align__(16) float g_Xi[NODE_PAD * HDIM];
__device__ __align__(16) float g_Xt[NODE_PAD * HDIM];
__device__ __align__(16) float g_Xu[NODE_PAD * HDIM];
__device__ __align__(16) float g_Xt2[NODE_PAD * HDIM];
__device__ __align__(16) float g_Xu2[NODE_PAD * HDIM];
__device__ __align__(16) float g_Er[(size_t)EDGE_PAD * OUT_F];
__device__ __align__(16) float g_Ei[(size_t)EDGE_PAD * OUT_F];
__device__ __align__(16) float g_Yt[(size_t)EDGE_PAD * HDIM];
__device__ __align__(16) float g_Yu[(size_t)EDGE_PAD * HDIM];
__device__ __align__(16) float g_Zt[(size_t)EDGE_PAD * HDIM];
__device__ __align__(16) float g_Zu[(size_t)EDGE_PAD * HDIM];
__device__ int g_row[N_EDGES];
__device__ int g_col[N_EDGES];
__device__ int g_is64;
#define W_TOTAL 253952
__device__ __align__(16) float g_Wt[W_TOTAL];
#define OFF_WN   0
#define OFF_WE   4096
#define OFF_NW   8192
#define OFF_NOW  118784
#define OFF_EW   131072
#define OFF_EOW  241664

// -------------------- helpers ------------------------------------------------
__device__ __forceinline__ uint32_t smem_u32(const void* p) {
    uint32_t a;
    asm("{ .reg .u64 t; cvta.to.shared.u64 t, %1; cvt.u32.u64 %0, t; }"
        : "=r"(a) : "l"(p));
    return a;
}

__device__ __forceinline__ float tf32r(float f) {
    uint32_t r;
    asm("cvt.rna.tf32.f32 %0, %1;" : "=r"(r) : "f"(f));
    return __uint_as_float(r);
}

__device__ __forceinline__ void ldsm_x4(uint32_t& r0, uint32_t& r1,
                                        uint32_t& r2, uint32_t& r3,
                                        uint32_t addr) {
    asm volatile("ldmatrix.sync.aligned.m8n8.x4.shared.b16 {%0,%1,%2,%3}, [%4];"
                 : "=r"(r0), "=r"(r1), "=r"(r2), "=r"(r3) : "r"(addr));
}

__device__ __forceinline__ void mma_tf32(float* c, const uint32_t* a,
                                         const uint32_t* b) {
    asm volatile(
        "mma.sync.aligned.m16n8k8.row.col.f32.tf32.tf32.f32 "
        "{%0,%1,%2,%3}, {%4,%5,%6,%7}, {%8,%9}, {%0,%1,%2,%3};"
        : "+f"(c[0]), "+f"(c[1]), "+f"(c[2]), "+f"(c[3])
        : "r"(a[0]), "r"(a[1]), "r"(a[2]), "r"(a[3]), "r"(b[0]), "r"(b[1]));
}

__device__ __forceinline__ void cp16(uint32_t dst, const void* src) {
    asm volatile("cp.async.cg.shared.global [%0], [%1], 16;"
                 :: "r"(dst), "l"(src));
}

// -------------------- edge_index dtype detection + conversion ---------------
__global__ void k_detect(const unsigned int* __restrict__ p) {
    if (threadIdx.x == 0) {
        int all_zero = 1;
        for (int i = 0; i < 128; ++i)
            if (p[2 * i + 1] != 0u) { all_zero = 0; break; }
        g_is64 = all_zero;
    }
}

__global__ void k_convert(const void* __restrict__ raw) {
    int e = blockIdx.x * blockDim.x + threadIdx.x;
    if (e >= N_EDGES) return;
    if (g_is64) {
        const long long* p = (const long long*)raw;
        g_row[e] = (int)p[2 * e];
        g_col[e] = (int)p[2 * e + 1];
    } else {
        const int* p = (const int*)raw;
        g_row[e] = p[2 * e];
        g_col[e] = p[2 * e + 1];
    }
}

// -------------------- weight prep: round to tf32 once ------------------------
__global__ void k_prepW(const float* s0, const float* s1, const float* s2,
                        const float* s3, const float* s4, const float* s5) {
    const int sizes[6] = {4096, 4096, 110592, 12288, 110592, 12288};
    const int offs[6]  = {OFF_WN, OFF_WE, OFF_NW, OFF_NOW, OFF_EW, OFF_EOW};
    int t = blockIdx.y;
    const float* s = (t == 0) ? s0 : (t == 1) ? s1 : (t == 2) ? s2
                   : (t == 3) ? s3 : (t == 4) ? s4 : s5;
    for (int i = blockIdx.x * blockDim.x + threadIdx.x; i < sizes[t];
         i += gridDim.x * blockDim.x)
        g_Wt[offs[t] + i] = tf32r(s[i]);
}

// zero only cols 64:192 (projection overwrites cols 0:64)
__global__ void k_zeroX() {
    int i = blockIdx.x * blockDim.x + threadIdx.x;
    if (i < N_NODES * 128) {
        int node = i >> 7, f = i & 127;
        g_Xr[(size_t)node * HDIM + 64 + f] = 0.f;
        g_Xi[(size_t)node * HDIM + 64 + f] = 0.f;
    }
}

// -------------------- merged projection (K=64): real+imag per CTA -----------
__global__ __launch_bounds__(256)
void k_proj2(const float* __restrict__ Ar, const float* __restrict__ Ai,
             int M, const float* __restrict__ W,
             const float* __restrict__ bias,
             float* __restrict__ Cr, float* __restrict__ Ci, int ldc)
{
    constexpr int K = 64, KPAD = 68, vpr = 16;
    extern __shared__ __align__(16) char smem[];
    float* As0 = reinterpret_cast<float*>(smem);
    float* As1 = As0 + 64 * KPAD;
    float* Bs  = As1 + 64 * KPAD;
    const uint32_t Bs32 = smem_u32(Bs);

    const int tid = threadIdx.x, lane = tid & 31, wid = tid >> 5;
    const int wm = wid >> 2, wn = wid & 3;
    const int bm = blockIdx.x * 64;

    for (int idx = tid; idx < 64 * vpr; idx += 256) {
        int n = idx / vpr, c4 = (idx - n * vpr) * 4;
        cp16(Bs32 + (uint32_t)((n * KPAD + c4) * 4), W + (size_t)n * K + c4);
    }
    asm volatile("cp.async.commit_group;");

    for (int idx = tid; idx < 64 * vpr; idx += 256) {
        int row = idx / vpr, c4 = (idx - row * vpr) * 4, gm = bm + row;
        float4 vr = make_float4(0.f, 0.f, 0.f, 0.f);
        float4 vi = make_float4(0.f, 0.f, 0.f, 0.f);
        if (gm < M) {
            vr = *reinterpret_cast<const float4*>(Ar + (size_t)gm * K + c4);
            vi = *reinterpret_cast<const float4*>(Ai + (size_t)gm * K + c4);
        }
        *reinterpret_cast<float4*>(As0 + row * KPAD + c4) =
            make_float4(tf32r(vr.x), tf32r(vr.y), tf32r(vr.z), tf32r(vr.w));
        *reinterpret_cast<float4*>(As1 + row * KPAD + c4) =
            make_float4(tf32r(vi.x), tf32r(vi.y), tf32r(vi.z), tf32r(vi.w));
    }
    asm volatile("cp.async.wait_group 0;");
    __syncthreads();

    const int nOff = (lane & 7) + ((lane >> 4) & 1) * 8;
    const uint32_t bAddr = Bs32 +
        (uint32_t)(((wn * 16 + nOff) * KPAD + ((lane >> 3) & 1) * 4) * 4);
    const uint32_t aLane =
        (uint32_t)(((wm * 32 + (lane & 15)) * KPAD + (lane >> 4) * 4) * 4);

#pragma unroll
    for (int h = 0; h < 2; ++h) {
        const uint32_t aAddr = smem_u32(h ? As1 : As0) + aLane;
        float* C = h ? Ci : Cr;

        float c[2][2][4];
#pragma unroll
        for (int i = 0; i < 2; ++i)
#pragma unroll
            for (int j = 0; j < 2; ++j)
#pragma unroll
                for (int q = 0; q < 4; ++q) c[i][j][q] = 0.f;

#pragma unroll
        for (int ks = 0; ks < K / 8; ++ks) {
            const uint32_t kb = (uint32_t)(ks * 32);
            uint32_t a0[4], a1[4], b[4];
            ldsm_x4(a0[0], a0[1], a0[2], a0[3], aAddr + kb);
            ldsm_x4(a1[0], a1[1], a1[2], a1[3],
                    aAddr + (uint32_t)(16 * KPAD * 4) + kb);
            ldsm_x4(b[0], b[1], b[2], b[3], bAddr + kb);
            mma_tf32(c[0][0], a0, b);
            mma_tf32(c[0][1], a0, b + 2);
            mma_tf32(c[1][0], a1, b);
            mma_tf32(c[1][1], a1, b + 2);
        }

#pragma unroll
        for (int nt = 0; nt < 2; ++nt) {
            int col = wn * 16 + nt * 8 + (lane & 3) * 2;
            float bx = __ldg(bias + col);
            float by = __ldg(bias + col + 1);
#pragma unroll
            for (int mt = 0; mt < 2; ++mt) {
                int row0 = bm + wm * 32 + mt * 16 + (lane >> 2);
                float v0 = tf32r(c[mt][nt][0] + bx);
                float v1 = tf32r(c[mt][nt][1] + by);
                float v2 = tf32r(c[mt][nt][2] + bx);
                float v3 = tf32r(c[mt][nt][3] + by);
                if (row0 < M)
                    *reinterpret_cast<float2*>(C + (size_t)row0 * ldc + col) =
                        make_float2(v0, v1);
                if (row0 + 8 < M)
                    *reinterpret_cast<float2*>(C + (size_t)(row0 + 8) * ldc + col) =
                        make_float2(v2, v3);
            }
        }
    }
}

// -------------------- big layer (NOUT=192): 128-row tiles, 512 threads ------
// blockIdx.y selects stream (0=real, 1=imag).
// MODE 0: A via cp.async (pre-rounded).  MODE 1: gather concat(E,H[row],H[col]).
// MODE 2: A cvt-staged (raw fp32, contiguous K=192).
template <int MODE>
__global__ __launch_bounds__(512, 1)
void k_layer512(const float* __restrict__ A0, const float* __restrict__ A1,
                int M,
                const float* __restrict__ W,
                const float* __restrict__ bias,
                const float* __restrict__ alphaPtr,
                float* __restrict__ C0, float* __restrict__ C1,
                const float* __restrict__ GH0, const float* __restrict__ GH1)
{
    constexpr int K = 192, KC = 48, KCPAD = 52, NCH = K / KC;
    constexpr int NOUT = 192, NW = 48, NB = 3;
    constexpr int CHF = (128 + NOUT) * KCPAD;          // floats per buffer
    extern __shared__ __align__(16) char smem[];
    float* buf0 = reinterpret_cast<float*>(smem);

    const int tid = threadIdx.x, lane = tid & 31, wid = tid >> 5;
    const int wm = wid >> 2, wn = wid & 3;              // 4m x 4n
    const int bm = blockIdx.x * 128;
    const float* A  = blockIdx.y ? A1 : A0;
    float*       C  = blockIdx.y ? C1 : C0;
    const float* GH = blockIdx.y ? GH1 : GH0;

    auto stage = [&](int c, int b) {
        float* bufA = buf0 + b * CHF;
        float* bufB = bufA + 128 * KCPAD;
        const uint32_t A32 = smem_u32(bufA);
        const uint32_t B32 = smem_u32(bufB);
        if (MODE == 0) {
#pragma unroll
            for (int it = 0; it < 3; ++it) {
                int idx = tid + it * 512;               // 0..1535
                int row = idx / 12, q = idx - row * 12;
                int gm = bm + row; if (gm > M - 1) gm = M - 1;
                cp16(A32 + (uint32_t)((row * KCPAD + q * 4) * 4),
                     A + (size_t)gm * K + c * KC + q * 4);
            }
        } else if (MODE == 1) {
#pragma unroll
            for (int it = 0; it < 3; ++it) {
                int idx = tid + it * 512;
                int row = idx / 12, q = idx - row * 12;
                int e = bm + row; if (e > M - 1) e = M - 1;
                int gcol = c * KC + q * 4;
                int seg = gcol >> 6, off = gcol & 63;
                const float* src;
                if (seg == 0) {
                    src = A + (size_t)e * 64 + off;
                } else {
                    int n = (seg == 1) ? __ldg(&g_row[e]) : __ldg(&g_col[e]);
                    src = GH + (size_t)n * 64 + off;
                }
                float4 v = *reinterpret_cast<const float4*>(src);
                *reinterpret_cast<float4*>(bufA + row * KCPAD + q * 4) =
                    make_float4(tf32r(v.x), tf32r(v.y), tf32r(v.z), tf32r(v.w));
            }
        } else {
#pragma unroll
            for (int it = 0; it < 3; ++it) {
                int idx = tid + it * 512;
                int row = idx / 12, q = idx - row * 12;
                int gm = bm + row; if (gm > M - 1) gm = M - 1;
                float4 v = *reinterpret_cast<const float4*>(
                    A + (size_t)gm * K + c * KC + q * 4);
                *reinterpret_cast<float4*>(bufA + row * KCPAD + q * 4) =
                    make_float4(tf32r(v.x), tf32r(v.y), tf32r(v.z), tf32r(v.w));
            }
        }
        // B chunk: 192 x 48 -> 2304 float4 over 512 threads
        for (int idx = tid; idx < NOUT * 12; idx += 512) {
            int n = idx / 12, q = idx - n * 12;
            cp16(B32 + (uint32_t)((n * KCPAD + q * 4) * 4),
                 W + (size_t)n * K + c * KC + q * 4);
        }
        asm volatile("cp.async.commit_group;");
    };

    const uint32_t aLaneOff =
        (uint32_t)(((wm * 32 + (lane & 15)) * KCPAD + (lane >> 4) * 4) * 4);
    const int nOff = (lane & 7) + ((lane >> 4) & 1) * 8;
    const int kcol = ((lane >> 3) & 1) * 4;
    uint32_t bLaneOff[NB];
#pragma unroll
    for (int j = 0; j < NB; ++j)
        bLaneOff[j] = (uint32_t)(((wn * NW + j * 16 + nOff) * KCPAD + kcol) * 4);

    float acc[2][NB * 2][4];
#pragma unroll
    for (int x = 0; x < 2; ++x)
#pragma unroll
        for (int y = 0; y < NB * 2; ++y)
#pragma unroll
            for (int q = 0; q < 4; ++q) acc[x][y][q] = 0.f;

    stage(0, 0);

#pragma unroll
    for (int c = 0; c < NCH; ++c) {
        if (c + 1 < NCH) {
            stage(c + 1, (c + 1) & 1);
            asm volatile("cp.async.wait_group 1;");
        } else {
            asm volatile("cp.async.wait_group 0;");
        }
        __syncthreads();

        float* bufA = buf0 + (c & 1) * CHF;
        const uint32_t B32 = smem_u32(bufA + 128 * KCPAD);
        const uint32_t aAddr = smem_u32(bufA) + aLaneOff;

#pragma unroll
        for (int ks = 0; ks < KC / 8; ++ks) {
            const uint32_t kb = (uint32_t)(ks * 32);
            uint32_t a0[4], a1[4];
            ldsm_x4(a0[0], a0[1], a0[2], a0[3], aAddr + kb);
            ldsm_x4(a1[0], a1[1], a1[2], a1[3],
                    aAddr + (uint32_t)(16 * KCPAD * 4) + kb);
#pragma unroll
            for (int j = 0; j < NB; ++j) {
                uint32_t b[4];
                ldsm_x4(b[0], b[1], b[2], b[3], B32 + bLaneOff[j] + kb);
                mma_tf32(acc[0][2 * j + 0], a0, b);
                mma_tf32(acc[0][2 * j + 1], a0, b + 2);
                mma_tf32(acc[1][2 * j + 0], a1, b);
                mma_tf32(acc[1][2 * j + 1], a1, b + 2);
            }
        }
        __syncthreads();
    }

    const float al = __ldg(alphaPtr);
#pragma unroll
    for (int nf = 0; nf < NB * 2; ++nf) {
        int col = wn * NW + nf * 8 + (lane & 3) * 2;
        float bx = __ldg(bias + col);
        float by = __ldg(bias + col + 1);
#pragma unroll
        for (int mf = 0; mf < 2; ++mf) {
            int row0 = bm + wm * 32 + mf * 16 + (lane >> 2);
            float v0 = acc[mf][nf][0] + bx;
            float v1 = acc[mf][nf][1] + by;
            float v2 = acc[mf][nf][2] + bx;
            float v3 = acc[mf][nf][3] + by;
            v0 = (v0 >= 0.f) ? v0 : al * v0;
            v1 = (v1 >= 0.f) ? v1 : al * v1;
            v2 = (v2 >= 0.f) ? v2 : al * v2;
            v3 = (v3 >= 0.f) ? v3 : al * v3;
            v0 = tf32r(v0); v1 = tf32r(v1);
            v2 = tf32r(v2); v3 = tf32r(v3);
            if (row0 < M)
                *reinterpret_cast<float2*>(C + (size_t)row0 * NOUT + col) =
                    make_float2(v0, v1);
            if (row0 + 8 < M)
                *reinterpret_cast<float2*>(C + (size_t)(row0 + 8) * NOUT + col) =
                    make_float2(v2, v3);
        }
    }
}

// -------------------- out layer (NOUT=64): 64-row tiles, 256 threads --------
__global__ __launch_bounds__(256, 2)
void k_out(const float* __restrict__ A0, const float* __restrict__ A1,
           int M,
           const float* __restrict__ W,
           const float* __restrict__ bias,
           float* __restrict__ C0, float* __restrict__ C1)
{
    constexpr int K = 192, KC = 48, KCPAD = 52, NCH = K / KC;
    constexpr int NOUT = 64, NW = 16, NB = 1;
    constexpr int CHF = (64 + NOUT) * KCPAD;
    extern __shared__ __align__(16) char smem[];
    float* buf0 = reinterpret_cast<float*>(smem);

    const int tid = threadIdx.x, lane = tid & 31, wid = tid >> 5;
    const int wm = wid >> 2, wn = wid & 3;
    const int bm = blockIdx.x * 64;
    const float* A = blockIdx.y ? A1 : A0;
    float*       C = blockIdx.y ? C1 : C0;

    auto stage = [&](int c, int b) {
        float* bufA = buf0 + b * CHF;
        const uint32_t A32 = smem_u32(bufA);
        const uint32_t B32 = smem_u32(bufA + 64 * KCPAD);
#pragma unroll
        for (int it = 0; it < 3; ++it) {
            int idx = tid + it * 256;
            int row = idx / 12, q = idx - row * 12;
            int gm = bm + row; if (gm > M - 1) gm = M - 1;
            cp16(A32 + (uint32_t)((row * KCPAD + q * 4) * 4),
                 A + (size_t)gm * K + c * KC + q * 4);
        }
#pragma unroll
        for (int it = 0; it < 3; ++it) {
            int idx = tid + it * 256;
            int n = idx / 12, q = idx - n * 12;
            cp16(B32 + (uint32_t)((n * KCPAD + q * 4) * 4),
                 W + (size_t)n * K + c * KC + q * 4);
        }
        asm volatile("cp.async.commit_group;");
    };

    const uint32_t aLaneOff =
        (uint32_t)(((wm * 32 + (lane & 15)) * KCPAD + (lane >> 4) * 4) * 4);
    const int nOff = (lane & 7) + ((lane >> 4) & 1) * 8;
    const int kcol = ((lane >> 3) & 1) * 4;
    const uint32_t bLaneOff =
        (uint32_t)(((wn * NW + nOff) * KCPAD + kcol) * 4);

    float acc[2][2][4];
#pragma unroll
    for (int x = 0; x < 2; ++x)
#pragma unroll
        for (int y = 0; y < 2; ++y)
#pragma unroll
            for (int q = 0; q < 4; ++q) acc[x][y][q] = 0.f;

    stage(0, 0);

#pragma unroll
    for (int c = 0; c < NCH; ++c) {
        if (c + 1 < NCH) {
            stage(c + 1, (c + 1) & 1);
            asm volatile("cp.async.wait_group 1;");
        } else {
            asm volatile("cp.async.wait_group 0;");
        }
        __syncthreads();

        float* bufA = buf0 + (c & 1) * CHF;
        const uint32_t B32 = smem_u32(bufA + 64 * KCPAD);
        const uint32_t aAddr = smem_u32(bufA) + aLaneOff;

#pragma unroll
        for (int ks = 0; ks < KC / 8; ++ks) {
            const uint32_t kb = (uint32_t)(ks * 32);
            uint32_t a0[4], a1[4], b[4];
            ldsm_x4(a0[0], a0[1], a0[2], a0[3], aAddr + kb);
            ldsm_x4(a1[0], a1[1], a1[2], a1[3],
                    aAddr + (uint32_t)(16 * KCPAD * 4) + kb);
            ldsm_x4(b[0], b[1], b[2], b[3], B32 + bLaneOff + kb);
            mma_tf32(acc[0][0], a0, b);
            mma_tf32(acc[0][1], a0, b + 2);
            mma_tf32(acc[1][0], a1, b);
            mma_tf32(acc[1][1], a1, b + 2);
        }
        __syncthreads();
    }

#pragma unroll
    for (int nf = 0; nf < 2; ++nf) {
        int col = wn * NW + nf * 8 + (lane & 3) * 2;
        float bx = __ldg(bias + col);
        float by = __ldg(bias + col + 1);
#pragma unroll
        for (int mf = 0; mf < 2; ++mf) {
            int row0 = bm + wm * 32 + mf * 16 + (lane >> 2);
            float v0 = acc[mf][nf][0] + bx;
            float v1 = acc[mf][nf][1] + by;
            float v2 = acc[mf][nf][2] + bx;
            float v3 = acc[mf][nf][3] + by;
            if (row0 < M)
                *reinterpret_cast<float2*>(C + (size_t)row0 * NOUT + col) =
                    make_float2(v0, v1);
            if (row0 + 8 < M)
                *reinterpret_cast<float2*>(C + (size_t)(row0 + 8) * NOUT + col) =
                    make_float2(v2, v3);
        }
    }
}

// -------------------- node aggregation (segment-sum via atomics) ------------
__global__ void k_scatter() {
    int t = blockIdx.x * blockDim.x + threadIdx.x;
    if (t >= N_EDGES * IN_F) return;
    int e = t >> 6;
    int f = t & 63;
    int r = g_row[e];
    int c = g_col[e];

    float vnr = g_Xr[(size_t)c * HDIM + f];
    float vni = g_Xi[(size_t)c * HDIM + f];
    float ver = g_Er[(size_t)e * 64 + f];
    float vei = g_Ei[(size_t)e * 64 + f];

    atomicAdd(&g_Xr[(size_t)r * HDIM + 64  + f], vnr);
    atomicAdd(&g_Xr[(size_t)r * HDIM + 128 + f], ver);
    atomicAdd(&g_Xi[(size_t)r * HDIM + 64  + f], vni);
    atomicAdd(&g_Xi[(size_t)r * HDIM + 128 + f], vei);
}

// ---------------------------------------------------------------------------
static float* symaddr(const void* sym) {
    void* p = nullptr;
    cudaGetSymbolAddress(&p, sym);
    return (float*)p;
}

extern "C" void kernel_launch(void* const* d_in, const int* in_sizes, int n_in,
                              void* d_out, int out_size)
{
    const float* node_real = (const float*)d_in[0];
    const float* node_imag = (const float*)d_in[1];
    const float* edge_real = (const float*)d_in[2];
    const float* edge_imag = (const float*)d_in[3];
    const void*  edge_idx  = d_in[4];
    const float* Wn        = (const float*)d_in[5];
    const float* bn_       = (const float*)d_in[6];
    const float* We        = (const float*)d_in[7];
    const float* be_       = (const float*)d_in[8];
    const float* node_W    = (const float*)d_in[9];
    const float* node_b    = (const float*)d_in[10];
    const float* node_al   = (const float*)d_in[11];
    const float* node_oW   = (const float*)d_in[12];
    const float* node_ob   = (const float*)d_in[13];
    const float* edge_W    = (const float*)d_in[14];
    const float* edge_b    = (const float*)d_in[15];
    const float* edge_al   = (const float*)d_in[16];
    const float* edge_oW   = (const float*)d_in[17];
    const float* edge_ob   = (const float*)d_in[18];

    float* out  = (float*)d_out;
    float* hr   = out;
    float* hi   = out + (size_t)N_NODES * OUT_F;
    float* outr = out + 2 * (size_t)N_NODES * OUT_F;
    float* outi = outr + (size_t)N_EDGES * OUT_F;

    float* Xr  = symaddr(g_Xr);
    float* Xi  = symaddr(g_Xi);
    float* Xt  = symaddr(g_Xt);
    float* Xu  = symaddr(g_Xu);
    float* Xt2 = symaddr(g_Xt2);
    float* Xu2 = symaddr(g_Xu2);
    float* Er  = symaddr(g_Er);
    float* Ei  = symaddr(g_Ei);
    float* Yt  = symaddr(g_Yt);
    float* Yu  = symaddr(g_Yu);
    float* Zt  = symaddr(g_Zt);
    float* Zu  = symaddr(g_Zu);
    float* Wt  = symaddr(g_Wt);

    const int SMEM_PROJ2 = (128 + 64) * 68 * 4;         // 52.2 KB
    const int SMEM_BIG   = 2 * (128 + 192) * 52 * 4;    // 133.1 KB -> 1 CTA/SM
    const int SMEM_OUT   = 2 * (64 + 64) * 52 * 4;      // 53.2 KB -> 2 CTA/SM
    cudaFuncSetAttribute(k_proj2, cudaFuncAttributeMaxDynamicSharedMemorySize, SMEM_PROJ2);
    cudaFuncSetAttribute(k_layer512<0>, cudaFuncAttributeMaxDynamicSharedMemorySize, SMEM_BIG);
    cudaFuncSetAttribute(k_layer512<1>, cudaFuncAttributeMaxDynamicSharedMemorySize, SMEM_BIG);
    cudaFuncSetAttribute(k_layer512<2>, cudaFuncAttributeMaxDynamicSharedMemorySize, SMEM_BIG);
    cudaFuncSetAttribute(k_out, cudaFuncAttributeMaxDynamicSharedMemorySize, SMEM_OUT);

    const int TPB  = 256;
    const int gN64  = (N_NODES + 63) / 64;     // 391
    const int gE64  = N_EDGES / 64;            // 3125
    const int gN128 = (N_NODES + 127) / 128;   // 196
    const int gE128 = (N_EDGES + 127) / 128;   // 1563
    const int HH    = HDIM * HDIM;

    // 1-2. edge index conversion
    k_detect<<<1, 32>>>((const unsigned int*)edge_idx);
    k_convert<<<(N_EDGES + TPB - 1) / TPB, TPB>>>(edge_idx);

    // 3. weight prep (tf32 round)
    k_prepW<<<dim3(432, 6), TPB>>>(Wn, We, node_W, node_oW, edge_W, edge_oW);

    // 4. zero node agg region (cols 64:192 only)
    k_zeroX<<<(N_NODES * 128 + TPB - 1) / TPB, TPB>>>();

    // 5-6. merged projections (real+imag per CTA)
    k_proj2<<<gE64, TPB, SMEM_PROJ2>>>(edge_real, edge_imag, N_EDGES,
                                       Wt + OFF_WE, be_, Er, Ei, OUT_F);
    k_proj2<<<gN64, TPB, SMEM_PROJ2>>>(node_real, node_imag, N_NODES,
                                       Wt + OFF_WN, bn_, Xr, Xi, HDIM);

    // 7. node aggregation
    k_scatter<<<(N_EDGES * IN_F + TPB - 1) / TPB, TPB>>>();

    // 8-11. node MLP (real+imag merged)
    k_layer512<2><<<dim3(gN128, 2), 512, SMEM_BIG>>>(Xr, Xi, N_NODES,
        Wt + OFF_NW,        node_b,          node_al,     Xt, Xt2, nullptr, nullptr);
    k_layer512<0><<<dim3(gN128, 2), 512, SMEM_BIG>>>(Xt, Xt2, N_NODES,
        Wt + OFF_NW + HH,   node_b + HDIM,   node_al + 1, Xu, Xu2, nullptr, nullptr);
    k_layer512<0><<<dim3(gN128, 2), 512, SMEM_BIG>>>(Xu, Xu2, N_NODES,
        Wt + OFF_NW + 2*HH, node_b + 2*HDIM, node_al + 2, Xt, Xt2, nullptr, nullptr);
    k_out<<<dim3(gN64, 2), TPB, SMEM_OUT>>>(Xt, Xt2, N_NODES,
        Wt + OFF_NOW, node_ob, hr, hi);

    // 12-15. edge MLP (real+imag merged; layer1 gathers hr/hi)
    k_layer512<1><<<dim3(gE128, 2), 512, SMEM_BIG>>>(Er, Ei, N_EDGES,
        Wt + OFF_EW,        edge_b,          edge_al,     Yt, Zt, hr, hi);
    k_layer512<0><<<dim3(gE128, 2), 512, SMEM_BIG>>>(Yt, Zt, N_EDGES,
        Wt + OFF_EW + HH,   edge_b + HDIM,   edge_al + 1, Yu, Zu, nullptr, nullptr);
    k_layer512<0><<<dim3(gE128, 2), 512, SMEM_BIG>>>(Yu, Zu, N_EDGES,
        Wt + OFF_EW + 2*HH, edge_b + 2*HDIM, edge_al + 2, Yt, Zt, nullptr, nullptr);
    k_out<<<dim3(gE64, 2), TPB, SMEM_OUT>>>(Yt, Zt, N_EDGES,
        Wt + OFF_EOW, edge_ob, outr, outi);
}

// round 17
// speedup vs baseline: 1.0781x; 1.0781x over previous
#include <cuda_runtime.h>
#include <cstdint>

// ---------------------------------------------------------------------------
// MPEdgeNodeBlock — TF32 mma.sync, K-chunked double-buffered layers (R14
// structure: 64-row tiles, 256 thr, 2 CTA/SM — R15's 512-thr/1-CTA regressed).
// R16: layer-3 + out-layer FUSED: Wo prefetched into the freed double-buffer
// during the last K-chunk's compute; layer-3 activations stay in smem; out
// GEMM runs in-kernel.  Kills 2 launches + ~230MB activation round-trip.
// ---------------------------------------------------------------------------
#define N_NODES  25000
#define NODE_PAD 25024            // 391 * 64
#define N_EDGES  200000
#define IN_F     64
#define OUT_F    64
#define HDIM     192

// -------------------- scratch (device globals; no runtime alloc) ------------
__device__ __align__(16) float g_Xr[NODE_PAD * HDIM];
__device__ __align__(16) float g_Xi[NODE_PAD * HDIM];
__device__ __align__(16) float g_Xt[NODE_PAD * HDIM];
__device__ __align__(16) float g_Xu[NODE_PAD * HDIM];
__device__ __align__(16) float g_Xt2[NODE_PAD * HDIM];
__device__ __align__(16) float g_Xu2[NODE_PAD * HDIM];
__device__ __align__(16) float g_Er[(size_t)N_EDGES * OUT_F];
__device__ __align__(16) float g_Ei[(size_t)N_EDGES * OUT_F];
__device__ __align__(16) float g_Yt[(size_t)N_EDGES * HDIM];
__device__ __align__(16) float g_Yu[(size_t)N_EDGES * HDIM];
__device__ __align__(16) float g_Zt[(size_t)N_EDGES * HDIM];
__device__ __align__(16) float g_Zu[(size_t)N_EDGES * HDIM];
__device__ int g_row[N_EDGES];
__device__ int g_col[N_EDGES];
__device__ int g_is64;
#define W_TOTAL 253952
__device__ __align__(16) float g_Wt[W_TOTAL];
#define OFF_WN   0
#define OFF_WE   4096
#define OFF_NW   8192
#define OFF_NOW  118784
#define OFF_EW   131072
#define OFF_EOW  241664

// -------------------- helpers ------------------------------------------------
__device__ __forceinline__ uint32_t smem_u32(const void* p) {
    uint32_t a;
    asm("{ .reg .u64 t; cvta.to.shared.u64 t, %1; cvt.u32.u64 %0, t; }"
        : "=r"(a) : "l"(p));
    return a;
}

__device__ __forceinline__ float tf32r(float f) {
    uint32_t r;
    asm("cvt.rna.tf32.f32 %0, %1;" : "=r"(r) : "f"(f));
    return __uint_as_float(r);
}

__device__ __forceinline__ void ldsm_x4(uint32_t& r0, uint32_t& r1,
                                        uint32_t& r2, uint32_t& r3,
                                        uint32_t addr) {
    asm volatile("ldmatrix.sync.aligned.m8n8.x4.shared.b16 {%0,%1,%2,%3}, [%4];"
                 : "=r"(r0), "=r"(r1), "=r"(r2), "=r"(r3) : "r"(addr));
}

__device__ __forceinline__ void mma_tf32(float* c, const uint32_t* a,
                                         const uint32_t* b) {
    asm volatile(
        "mma.sync.aligned.m16n8k8.row.col.f32.tf32.tf32.f32 "
        "{%0,%1,%2,%3}, {%4,%5,%6,%7}, {%8,%9}, {%0,%1,%2,%3};"
        : "+f"(c[0]), "+f"(c[1]), "+f"(c[2]), "+f"(c[3])
        : "r"(a[0]), "r"(a[1]), "r"(a[2]), "r"(a[3]), "r"(b[0]), "r"(b[1]));
}

__device__ __forceinline__ void cp16(uint32_t dst, const void* src) {
    asm volatile("cp.async.cg.shared.global [%0], [%1], 16;"
                 :: "r"(dst), "l"(src));
}

// -------------------- edge_index dtype detection + conversion ---------------
__global__ void k_detect(const unsigned int* __restrict__ p) {
    if (threadIdx.x == 0) {
        int all_zero = 1;
        for (int i = 0; i < 128; ++i)
            if (p[2 * i + 1] != 0u) { all_zero = 0; break; }
        g_is64 = all_zero;
    }
}

__global__ void k_convert(const void* __restrict__ raw) {
    int e = blockIdx.x * blockDim.x + threadIdx.x;
    if (e >= N_EDGES) return;
    if (g_is64) {
        const long long* p = (const long long*)raw;
        g_row[e] = (int)p[2 * e];
        g_col[e] = (int)p[2 * e + 1];
    } else {
        const int* p = (const int*)raw;
        g_row[e] = p[2 * e];
        g_col[e] = p[2 * e + 1];
    }
}

// -------------------- weight prep: round to tf32 once ------------------------
__global__ void k_prepW(const float* s0, const float* s1, const float* s2,
                        const float* s3, const float* s4, const float* s5) {
    const int sizes[6] = {4096, 4096, 110592, 12288, 110592, 12288};
    const int offs[6]  = {OFF_WN, OFF_WE, OFF_NW, OFF_NOW, OFF_EW, OFF_EOW};
    int t = blockIdx.y;
    const float* s = (t == 0) ? s0 : (t == 1) ? s1 : (t == 2) ? s2
                   : (t == 3) ? s3 : (t == 4) ? s4 : s5;
    for (int i = blockIdx.x * blockDim.x + threadIdx.x; i < sizes[t];
         i += gridDim.x * blockDim.x)
        g_Wt[offs[t] + i] = tf32r(s[i]);
}

// zero only cols 64:192 (projection overwrites cols 0:64)
__global__ void k_zeroX() {
    int i = blockIdx.x * blockDim.x + threadIdx.x;
    if (i < N_NODES * 128) {
        int node = i >> 7, f = i & 127;
        g_Xr[(size_t)node * HDIM + 64 + f] = 0.f;
        g_Xi[(size_t)node * HDIM + 64 + f] = 0.f;
    }
}

// -------------------- merged projection (K=64): real+imag per CTA -----------
__global__ __launch_bounds__(256)
void k_proj2(const float* __restrict__ Ar, const float* __restrict__ Ai,
             int M, const float* __restrict__ W,
             const float* __restrict__ bias,
             float* __restrict__ Cr, float* __restrict__ Ci, int ldc)
{
    constexpr int K = 64, KPAD = 68, vpr = 16;
    extern __shared__ __align__(16) char smem[];
    float* As0 = reinterpret_cast<float*>(smem);
    float* As1 = As0 + 64 * KPAD;
    float* Bs  = As1 + 64 * KPAD;
    const uint32_t Bs32 = smem_u32(Bs);

    const int tid = threadIdx.x, lane = tid & 31, wid = tid >> 5;
    const int wm = wid >> 2, wn = wid & 3;
    const int bm = blockIdx.x * 64;

    for (int idx = tid; idx < 64 * vpr; idx += 256) {
        int n = idx / vpr, c4 = (idx - n * vpr) * 4;
        cp16(Bs32 + (uint32_t)((n * KPAD + c4) * 4), W + (size_t)n * K + c4);
    }
    asm volatile("cp.async.commit_group;");

    for (int idx = tid; idx < 64 * vpr; idx += 256) {
        int row = idx / vpr, c4 = (idx - row * vpr) * 4, gm = bm + row;
        float4 vr = make_float4(0.f, 0.f, 0.f, 0.f);
        float4 vi = make_float4(0.f, 0.f, 0.f, 0.f);
        if (gm < M) {
            vr = *reinterpret_cast<const float4*>(Ar + (size_t)gm * K + c4);
            vi = *reinterpret_cast<const float4*>(Ai + (size_t)gm * K + c4);
        }
        *reinterpret_cast<float4*>(As0 + row * KPAD + c4) =
            make_float4(tf32r(vr.x), tf32r(vr.y), tf32r(vr.z), tf32r(vr.w));
        *reinterpret_cast<float4*>(As1 + row * KPAD + c4) =
            make_float4(tf32r(vi.x), tf32r(vi.y), tf32r(vi.z), tf32r(vi.w));
    }
    asm volatile("cp.async.wait_group 0;");
    __syncthreads();

    const int nOff = (lane & 7) + ((lane >> 4) & 1) * 8;
    const uint32_t bAddr = Bs32 +
        (uint32_t)(((wn * 16 + nOff) * KPAD + ((lane >> 3) & 1) * 4) * 4);
    const uint32_t aLane =
        (uint32_t)(((wm * 32 + (lane & 15)) * KPAD + (lane >> 4) * 4) * 4);

#pragma unroll
    for (int h = 0; h < 2; ++h) {
        const uint32_t aAddr = smem_u32(h ? As1 : As0) + aLane;
        float* C = h ? Ci : Cr;

        float c[2][2][4];
#pragma unroll
        for (int i = 0; i < 2; ++i)
#pragma unroll
            for (int j = 0; j < 2; ++j)
#pragma unroll
                for (int q = 0; q < 4; ++q) c[i][j][q] = 0.f;

#pragma unroll
        for (int ks = 0; ks < K / 8; ++ks) {
            const uint32_t kb = (uint32_t)(ks * 32);
            uint32_t a0[4], a1[4], b[4];
            ldsm_x4(a0[0], a0[1], a0[2], a0[3], aAddr + kb);
            ldsm_x4(a1[0], a1[1], a1[2], a1[3],
                    aAddr + (uint32_t)(16 * KPAD * 4) + kb);
            ldsm_x4(b[0], b[1], b[2], b[3], bAddr + kb);
            mma_tf32(c[0][0], a0, b);
            mma_tf32(c[0][1], a0, b + 2);
            mma_tf32(c[1][0], a1, b);
            mma_tf32(c[1][1], a1, b + 2);
        }

#pragma unroll
        for (int nt = 0; nt < 2; ++nt) {
            int col = wn * 16 + nt * 8 + (lane & 3) * 2;
            float bx = __ldg(bias + col);
            float by = __ldg(bias + col + 1);
#pragma unroll
            for (int mt = 0; mt < 2; ++mt) {
                int row0 = bm + wm * 32 + mt * 16 + (lane >> 2);
                float v0 = tf32r(c[mt][nt][0] + bx);
                float v1 = tf32r(c[mt][nt][1] + by);
                float v2 = tf32r(c[mt][nt][2] + bx);
                float v3 = tf32r(c[mt][nt][3] + by);
                if (row0 < M)
                    *reinterpret_cast<float2*>(C + (size_t)row0 * ldc + col) =
                        make_float2(v0, v1);
                if (row0 + 8 < M)
                    *reinterpret_cast<float2*>(C + (size_t)(row0 + 8) * ldc + col) =
                        make_float2(v2, v3);
            }
        }
    }
}

// -------------------- K-chunked big layer (NOUT=192, merged real/imag) ------
// blockIdx.y selects stream.  MODE 0: cp.async A.  MODE 1: gather.  MODE 2:
// cvt-staged raw fp32.  FUSE=1: fused out-layer (Wo prefetched into freed
// buffer during last chunk; layer-3 acts stay in smem; out GEMM in-kernel).
template <int MODE, int FUSE>
__global__ __launch_bounds__(256, 2)
void k_layer(const float* __restrict__ A0, const float* __restrict__ A1,
             int M,
             const float* __restrict__ W,
             const float* __restrict__ bias,
             const float* __restrict__ alphaPtr,
             float* __restrict__ C0, float* __restrict__ C1,
             const float* __restrict__ GH0, const float* __restrict__ GH1,
             const float* __restrict__ Wo,      // FUSE: 64 x 192 (tf32)
             const float* __restrict__ bo)      // FUSE: 64
{
    constexpr int K = 192, KC = 48, KCPAD = 52, NCH = K / KC;
    constexpr int NW = 48, NB = 3;
    constexpr int CHF = (64 + 192) * KCPAD;       // 13312 floats per buffer
    constexpr int KP2 = 196;                      // fused-stage row pad
    extern __shared__ __align__(16) char smem[];
    float* buf0 = reinterpret_cast<float*>(smem);

    const int tid = threadIdx.x, lane = tid & 31, wid = tid >> 5;
    const int wm = wid >> 2, wn = wid & 3;
    const int bm = blockIdx.x * 64;
    const float* A  = blockIdx.y ? A1 : A0;
    float*       C  = blockIdx.y ? C1 : C0;
    const float* GH = blockIdx.y ? GH1 : GH0;

    auto stage = [&](int c, int b) {
        float* bufA = buf0 + b * CHF;
        float* bufB = bufA + 64 * KCPAD;
        const uint32_t A32 = smem_u32(bufA);
        const uint32_t B32 = smem_u32(bufB);
        if (MODE == 0) {
#pragma unroll
            for (int it = 0; it < 3; ++it) {
                int idx = tid + it * 256;
                int row = idx / 12, q = idx - row * 12;
                cp16(A32 + (uint32_t)((row * KCPAD + q * 4) * 4),
                     A + (size_t)(bm + row) * K + c * KC + q * 4);
            }
        } else if (MODE == 1) {
#pragma unroll
            for (int it = 0; it < 3; ++it) {
                int idx = tid + it * 256;
                int row = idx / 12, q = idx - row * 12;
                int e = bm + row;
                int gcol = c * KC + q * 4;
                int seg = gcol >> 6, off = gcol & 63;
                const float* src;
                if (seg == 0) {
                    src = A + (size_t)e * 64 + off;
                } else {
                    int n = (seg == 1) ? __ldg(&g_row[e]) : __ldg(&g_col[e]);
                    src = GH + (size_t)n * 64 + off;
                }
                float4 v = *reinterpret_cast<const float4*>(src);
                *reinterpret_cast<float4*>(bufA + row * KCPAD + q * 4) =
                    make_float4(tf32r(v.x), tf32r(v.y), tf32r(v.z), tf32r(v.w));
            }
        } else {
#pragma unroll
            for (int it = 0; it < 3; ++it) {
                int idx = tid + it * 256;
                int row = idx / 12, q = idx - row * 12;
                float4 v = *reinterpret_cast<const float4*>(
                    A + (size_t)(bm + row) * K + c * KC + q * 4);
                *reinterpret_cast<float4*>(bufA + row * KCPAD + q * 4) =
                    make_float4(tf32r(v.x), tf32r(v.y), tf32r(v.z), tf32r(v.w));
            }
        }
#pragma unroll
        for (int it = 0; it < 9; ++it) {          // B: 192 x 48 = 2304 float4
            int idx = tid + it * 256;
            int n = idx / 12, q = idx - n * 12;
            cp16(B32 + (uint32_t)((n * KCPAD + q * 4) * 4),
                 W + (size_t)n * K + c * KC + q * 4);
        }
        asm volatile("cp.async.commit_group;");
    };

    const uint32_t aLaneOff =
        (uint32_t)(((wm * 32 + (lane & 15)) * KCPAD + (lane >> 4) * 4) * 4);
    const int nOff = (lane & 7) + ((lane >> 4) & 1) * 8;
    const int kcol = ((lane >> 3) & 1) * 4;
    uint32_t bLaneOff[NB];
#pragma unroll
    for (int j = 0; j < NB; ++j)
        bLaneOff[j] = (uint32_t)(((wn * NW + j * 16 + nOff) * KCPAD + kcol) * 4);

    float acc[2][NB * 2][4];
#pragma unroll
    for (int x = 0; x < 2; ++x)
#pragma unroll
        for (int y = 0; y < NB * 2; ++y)
#pragma unroll
            for (int q = 0; q < 4; ++q) acc[x][y][q] = 0.f;

    stage(0, 0);

#pragma unroll
    for (int c = 0; c < NCH; ++c) {
        if (c + 1 < NCH) {
            stage(c + 1, (c + 1) & 1);
            asm volatile("cp.async.wait_group 1;");
        } else if (FUSE) {
            // prefetch Wo (64 x 192, KP2 pad) into now-free buffer 0
            const uint32_t Wo32 = smem_u32(buf0);
#pragma unroll
            for (int it = 0; it < 12; ++it) {     // 3072 float4
                int idx = tid + it * 256;
                int n = idx / 48, q = idx - n * 48;
                cp16(Wo32 + (uint32_t)((n * KP2 + q * 4) * 4),
                     Wo + (size_t)n * K + q * 4);
            }
            asm volatile("cp.async.commit_group;");
            asm volatile("cp.async.wait_group 1;");
        } else {
            asm volatile("cp.async.wait_group 0;");
        }
        __syncthreads();

        float* bufA = buf0 + (c & 1) * CHF;
        const uint32_t B32 = smem_u32(bufA + 64 * KCPAD);
        const uint32_t aAddr = smem_u32(bufA) + aLaneOff;

#pragma unroll
        for (int ks = 0; ks < KC / 8; ++ks) {
            const uint32_t kb = (uint32_t)(ks * 32);
            uint32_t a0[4], a1[4];
            ldsm_x4(a0[0], a0[1], a0[2], a0[3], aAddr + kb);
            ldsm_x4(a1[0], a1[1], a1[2], a1[3],
                    aAddr + (uint32_t)(16 * KCPAD * 4) + kb);
#pragma unroll
            for (int j = 0; j < NB; ++j) {
                uint32_t b[4];
                ldsm_x4(b[0], b[1], b[2], b[3], B32 + bLaneOff[j] + kb);
                mma_tf32(acc[0][2 * j + 0], a0, b);
                mma_tf32(acc[0][2 * j + 1], a0, b + 2);
                mma_tf32(acc[1][2 * j + 0], a1, b);
                mma_tf32(acc[1][2 * j + 1], a1, b + 2);
            }
        }
        __syncthreads();
    }

    const float al = __ldg(alphaPtr);
    float* actS = buf0 + CHF;                     // fused: acts into buffer 1

#pragma unroll
    for (int nf = 0; nf < NB * 2; ++nf) {
        int col = wn * NW + nf * 8 + (lane & 3) * 2;
        float bx = __ldg(bias + col);
        float by = __ldg(bias + col + 1);
#pragma unroll
        for (int mf = 0; mf < 2; ++mf) {
            int rloc = wm * 32 + mf * 16 + (lane >> 2);
            float v0 = acc[mf][nf][0] + bx;
            float v1 = acc[mf][nf][1] + by;
            float v2 = acc[mf][nf][2] + bx;
            float v3 = acc[mf][nf][3] + by;
            v0 = (v0 >= 0.f) ? v0 : al * v0;
            v1 = (v1 >= 0.f) ? v1 : al * v1;
            v2 = (v2 >= 0.f) ? v2 : al * v2;
            v3 = (v3 >= 0.f) ? v3 : al * v3;
            v0 = tf32r(v0); v1 = tf32r(v1);
            v2 = tf32r(v2); v3 = tf32r(v3);
            if (FUSE) {
                *reinterpret_cast<float2*>(actS + rloc * KP2 + col) =
                    make_float2(v0, v1);
                *reinterpret_cast<float2*>(actS + (rloc + 8) * KP2 + col) =
                    make_float2(v2, v3);
            } else {
                int row0 = bm + rloc;
                if (row0 < M)
                    *reinterpret_cast<float2*>(C + (size_t)row0 * 192 + col) =
                        make_float2(v0, v1);
                if (row0 + 8 < M)
                    *reinterpret_cast<float2*>(C + (size_t)(row0 + 8) * 192 + col) =
                        make_float2(v2, v3);
            }
        }
    }

    if (FUSE) {
        asm volatile("cp.async.wait_group 0;");   // Wo landed
        __syncthreads();                          // acts visible to all

        const uint32_t act32 = smem_u32(actS);
        const uint32_t Wo32  = smem_u32(buf0);
        const uint32_t aAddr2 = act32 +
            (uint32_t)(((wm * 32 + (lane & 15)) * KP2 + (lane >> 4) * 4) * 4);
        const uint32_t bAddr2 = Wo32 +
            (uint32_t)(((wn * 16 + nOff) * KP2 + kcol) * 4);

        float c2[2][2][4];
#pragma unroll
        for (int x = 0; x < 2; ++x)
#pragma unroll
            for (int y = 0; y < 2; ++y)
#pragma unroll
                for (int q = 0; q < 4; ++q) c2[x][y][q] = 0.f;

#pragma unroll
        for (int ks = 0; ks < 24; ++ks) {
            const uint32_t kb = (uint32_t)(ks * 32);
            uint32_t a0[4], a1[4], b[4];
            ldsm_x4(a0[0], a0[1], a0[2], a0[3], aAddr2 + kb);
            ldsm_x4(a1[0], a1[1], a1[2], a1[3],
                    aAddr2 + (uint32_t)(16 * KP2 * 4) + kb);
            ldsm_x4(b[0], b[1], b[2], b[3], bAddr2 + kb);
            mma_tf32(c2[0][0], a0, b);
            mma_tf32(c2[0][1], a0, b + 2);
            mma_tf32(c2[1][0], a1, b);
            mma_tf32(c2[1][1], a1, b + 2);
        }

#pragma unroll
        for (int nt = 0; nt < 2; ++nt) {
            int col = wn * 16 + nt * 8 + (lane & 3) * 2;
            float bx = __ldg(bo + col);
            float by = __ldg(bo + col + 1);
#pragma unroll
            for (int mt = 0; mt < 2; ++mt) {
                int row0 = bm + wm * 32 + mt * 16 + (lane >> 2);
                float v0 = c2[mt][nt][0] + bx;
                float v1 = c2[mt][nt][1] + by;
                float v2 = c2[mt][nt][2] + bx;
                float v3 = c2[mt][nt][3] + by;
                if (row0 < M)
                    *reinterpret_cast<float2*>(C + (size_t)row0 * 64 + col) =
                        make_float2(v0, v1);
                if (row0 + 8 < M)
                    *reinterpret_cast<float2*>(C + (size_t)(row0 + 8) * 64 + col) =
                        make_float2(v2, v3);
            }
        }
    }
}

// -------------------- node aggregation (segment-sum via atomics) ------------
__global__ void k_scatter() {
    int t = blockIdx.x * blockDim.x + threadIdx.x;
    if (t >= N_EDGES * IN_F) return;
    int e = t >> 6;
    int f = t & 63;
    int r = g_row[e];
    int c = g_col[e];

    float vnr = g_Xr[(size_t)c * HDIM + f];
    float vni = g_Xi[(size_t)c * HDIM + f];
    float ver = g_Er[(size_t)e * 64 + f];
    float vei = g_Ei[(size_t)e * 64 + f];

    atomicAdd(&g_Xr[(size_t)r * HDIM + 64  + f], vnr);
    atomicAdd(&g_Xr[(size_t)r * HDIM + 128 + f], ver);
    atomicAdd(&g_Xi[(size_t)r * HDIM + 64  + f], vni);
    atomicAdd(&g_Xi[(size_t)r * HDIM + 128 + f], vei);
}

// ---------------------------------------------------------------------------
static float* symaddr(const void* sym) {
    void* p = nullptr;
    cudaGetSymbolAddress(&p, sym);
    return (float*)p;
}

extern "C" void kernel_launch(void* const* d_in, const int* in_sizes, int n_in,
                              void* d_out, int out_size)
{
    const float* node_real = (const float*)d_in[0];
    const float* node_imag = (const float*)d_in[1];
    const float* edge_real = (const float*)d_in[2];
    const float* edge_imag = (const float*)d_in[3];
    const void*  edge_idx  = d_in[4];
    const float* Wn        = (const float*)d_in[5];
    const float* bn_       = (const float*)d_in[6];
    const float* We        = (const float*)d_in[7];
    const float* be_       = (const float*)d_in[8];
    const float* node_W    = (const float*)d_in[9];
    const float* node_b    = (const float*)d_in[10];
    const float* node_al   = (const float*)d_in[11];
    const float* node_oW   = (const float*)d_in[12];
    const float* node_ob   = (const float*)d_in[13];
    const float* edge_W    = (const float*)d_in[14];
    const float* edge_b    = (const float*)d_in[15];
    const float* edge_al   = (const float*)d_in[16];
    const float* edge_oW   = (const float*)d_in[17];
    const float* edge_ob   = (const float*)d_in[18];

    float* out  = (float*)d_out;
    float* hr   = out;
    float* hi   = out + (size_t)N_NODES * OUT_F;
    float* outr = out + 2 * (size_t)N_NODES * OUT_F;
    float* outi = outr + (size_t)N_EDGES * OUT_F;

    float* Xr  = symaddr(g_Xr);
    float* Xi  = symaddr(g_Xi);
    float* Xt  = symaddr(g_Xt);
    float* Xu  = symaddr(g_Xu);
    float* Xt2 = symaddr(g_Xt2);
    float* Xu2 = symaddr(g_Xu2);
    float* Er  = symaddr(g_Er);
    float* Ei  = symaddr(g_Ei);
    float* Yt  = symaddr(g_Yt);
    float* Yu  = symaddr(g_Yu);
    float* Zt  = symaddr(g_Zt);
    float* Zu  = symaddr(g_Zu);
    float* Wt  = symaddr(g_Wt);

    const int SMEM_PROJ2 = (128 + 64) * 68 * 4;         // 52.2 KB
    const int SMEM_L192  = 2 * (64 + 192) * 52 * 4;     // 106.5 KB -> 2 CTA/SM
    cudaFuncSetAttribute(k_proj2, cudaFuncAttributeMaxDynamicSharedMemorySize, SMEM_PROJ2);
    cudaFuncSetAttribute(k_layer<0, 0>, cudaFuncAttributeMaxDynamicSharedMemorySize, SMEM_L192);
    cudaFuncSetAttribute(k_layer<1, 0>, cudaFuncAttributeMaxDynamicSharedMemorySize, SMEM_L192);
    cudaFuncSetAttribute(k_layer<2, 0>, cudaFuncAttributeMaxDynamicSharedMemorySize, SMEM_L192);
    cudaFuncSetAttribute(k_layer<0, 1>, cudaFuncAttributeMaxDynamicSharedMemorySize, SMEM_L192);

    const int TPB = 256;
    const int gN  = (N_NODES + 63) / 64;   // 391
    const int gE  = N_EDGES / 64;          // 3125
    const int HH  = HDIM * HDIM;

    // 1-2. edge index conversion
    k_detect<<<1, 32>>>((const unsigned int*)edge_idx);
    k_convert<<<(N_EDGES + TPB - 1) / TPB, TPB>>>(edge_idx);

    // 3. weight prep (tf32 round)
    k_prepW<<<dim3(432, 6), TPB>>>(Wn, We, node_W, node_oW, edge_W, edge_oW);

    // 4. zero node agg region (cols 64:192 only)
    k_zeroX<<<(N_NODES * 128 + TPB - 1) / TPB, TPB>>>();

    // 5-6. merged projections (real+imag per CTA)
    k_proj2<<<gE, TPB, SMEM_PROJ2>>>(edge_real, edge_imag, N_EDGES,
                                     Wt + OFF_WE, be_, Er, Ei, OUT_F);
    k_proj2<<<gN, TPB, SMEM_PROJ2>>>(node_real, node_imag, N_NODES,
                                     Wt + OFF_WN, bn_, Xr, Xi, HDIM);

    // 7. node aggregation
    k_scatter<<<(N_EDGES * IN_F + TPB - 1) / TPB, TPB>>>();

    // 8-10. node MLP (real+imag merged; layer3+out fused -> hr/hi)
    k_layer<2, 0><<<dim3(gN, 2), TPB, SMEM_L192>>>(Xr, Xi, N_NODES,
        Wt + OFF_NW,        node_b,          node_al,     Xt, Xt2,
        nullptr, nullptr, nullptr, nullptr);
    k_layer<0, 0><<<dim3(gN, 2), TPB, SMEM_L192>>>(Xt, Xt2, N_NODES,
        Wt + OFF_NW + HH,   node_b + HDIM,   node_al + 1, Xu, Xu2,
        nullptr, nullptr, nullptr, nullptr);
    k_layer<0, 1><<<dim3(gN, 2), TPB, SMEM_L192>>>(Xu, Xu2, N_NODES,
        Wt + OFF_NW + 2*HH, node_b + 2*HDIM, node_al + 2, hr, hi,
        nullptr, nullptr, Wt + OFF_NOW, node_ob);

    // 11-13. edge MLP (real+imag merged; layer1 gathers; layer3+out fused)
    k_layer<1, 0><<<dim3(gE, 2), TPB, SMEM_L192>>>(Er, Ei, N_EDGES,
        Wt + OFF_EW,        edge_b,          edge_al,     Yt, Zt,
        hr, hi, nullptr, nullptr);
    k_layer<0, 0><<<dim3(gE, 2), TPB, SMEM_L192>>>(Yt, Zt, N_EDGES,
        Wt + OFF_EW + HH,   edge_b + HDIM,   edge_al + 1, Yu, Zu,
        nullptr, nullptr, nullptr, nullptr);
    k_layer<0, 1><<<dim3(gE, 2), TPB, SMEM_L192>>>(Yu, Zu, N_EDGES,
        Wt + OFF_EW + 2*HH, edge_b + 2*HDIM, edge_al + 2, outr, outi,
        nullptr, nullptr, Wt + OFF_EOW, edge_ob);
}